// round 1
// baseline (speedup 1.0000x reference)
#include <cuda_runtime.h>
#include <cuda_bf16.h>

// Problem constants (fixed by reference)
#define BB 32
#define TT 256
#define CC 512
#define LL 25

// Scratch in device globals (no allocations allowed in kernel_launch)
__device__ float g_wf[BB * TT * CC];        // 16 MB: post-FC features
__device__ float g_scores[BB * LL * TT];    // 0.8 MB: attention logits

// ---------------------------------------------------------------------------
// Eigen-style rational tanh: 10 FFMA + 1 approx-div (MUFU.RCP). |err| ~1e-6.
// ---------------------------------------------------------------------------
__device__ __forceinline__ float fast_tanh(float x) {
    x = fminf(fmaxf(x, -7.90531110763549805f), 7.90531110763549805f);
    float x2 = x * x;
    float p = fmaf(x2, -2.76076847742355e-16f, 2.00018790482477e-13f);
    p = fmaf(p, x2, -8.60467152213735e-11f);
    p = fmaf(p, x2, 5.12229709037114e-08f);
    p = fmaf(p, x2, 1.48572235717979e-05f);
    p = fmaf(p, x2, 6.37261928875436e-04f);
    p = fmaf(p, x2, 4.89352455891786e-03f);
    p = x * p;
    float q = fmaf(x2, 1.19825839466702e-06f, 1.18534705686654e-04f);
    q = fmaf(q, x2, 2.26843463243900e-03f);
    q = fmaf(q, x2, 4.89352518554385e-03f);
    return __fdividef(p, q);
}

// ---------------------------------------------------------------------------
// Kernel A: wf[m, n] = sum_k X[m,k] * W[n,k] + bias[n]
// M=8192, N=512, K=512. 128x128 block tile, 8x8 thread tile, BK=8.
// ---------------------------------------------------------------------------
__global__ __launch_bounds__(256) void wf_gemm_kernel(
    const float* __restrict__ X,     // [8192, 512]
    const float* __restrict__ W,     // [512, 512]  (row n, col k)
    const float* __restrict__ bias)  // [512]
{
    constexpr int K = CC;
    constexpr int N = CC;
    __shared__ float As[8][128];
    __shared__ float Bs[8][128];

    const int tid = threadIdx.x;
    const int m0 = blockIdx.y * 128;
    const int n0 = blockIdx.x * 128;
    const int tx = tid & 15;   // n direction (x8)
    const int ty = tid >> 4;   // m direction (x8)

    const int ldr = tid >> 1;          // 0..127 row within tile
    const int ldc = (tid & 1) << 2;    // 0 or 4 (k offset)

    const float* Ag = X + (m0 + ldr) * K + ldc;
    const float* Wg = W + (n0 + ldr) * K + ldc;

    float acc[8][8];
#pragma unroll
    for (int i = 0; i < 8; i++)
#pragma unroll
        for (int j = 0; j < 8; j++) acc[i][j] = 0.f;

    for (int k0 = 0; k0 < K; k0 += 8) {
        float4 av = *(const float4*)(Ag + k0);
        float4 bv = *(const float4*)(Wg + k0);
        __syncthreads();  // previous compute done before overwrite
        As[ldc + 0][ldr] = av.x;
        As[ldc + 1][ldr] = av.y;
        As[ldc + 2][ldr] = av.z;
        As[ldc + 3][ldr] = av.w;
        Bs[ldc + 0][ldr] = bv.x;
        Bs[ldc + 1][ldr] = bv.y;
        Bs[ldc + 2][ldr] = bv.z;
        Bs[ldc + 3][ldr] = bv.w;
        __syncthreads();
#pragma unroll
        for (int kk = 0; kk < 8; kk++) {
            float ar[8], br[8];
            *(float4*)&ar[0] = *(const float4*)&As[kk][ty * 8];
            *(float4*)&ar[4] = *(const float4*)&As[kk][ty * 8 + 4];
            *(float4*)&br[0] = *(const float4*)&Bs[kk][tx * 8];
            *(float4*)&br[4] = *(const float4*)&Bs[kk][tx * 8 + 4];
#pragma unroll
            for (int i = 0; i < 8; i++)
#pragma unroll
                for (int j = 0; j < 8; j++)
                    acc[i][j] = fmaf(ar[i], br[j], acc[i][j]);
        }
    }

    // Epilogue: add bias, store float4
#pragma unroll
    for (int i = 0; i < 8; i++) {
        int m = m0 + ty * 8 + i;
#pragma unroll
        for (int j4 = 0; j4 < 8; j4 += 4) {
            int n = n0 + tx * 8 + j4;
            float4 o;
            o.x = acc[i][j4 + 0] + bias[n + 0];
            o.y = acc[i][j4 + 1] + bias[n + 1];
            o.z = acc[i][j4 + 2] + bias[n + 2];
            o.w = acc[i][j4 + 3] + bias[n + 3];
            *(float4*)&g_wf[m * N + n] = o;
        }
    }
}

// ---------------------------------------------------------------------------
// Kernel B1: scores[b,l,t] = sum_c tanh(wf[b,t,c] + pos[l,c]) * aw[c] + ab
// One warp per (b,t) row; wf + atten_w live in registers for all 25 l's.
// pos_emb (50KB) stays hot in L1. grid = (T/8, B), 256 threads.
// ---------------------------------------------------------------------------
__global__ __launch_bounds__(256) void scores_kernel(
    const float* __restrict__ pos_emb,   // [25, 512]
    const float* __restrict__ atten_w,   // [512]
    const float* __restrict__ atten_b)   // [1]
{
    const int warp = threadIdx.x >> 5;
    const int lane = threadIdx.x & 31;
    const int b = blockIdx.y;
    const int t = blockIdx.x * 8 + warp;

    const float4* wfr = (const float4*)(g_wf + (b * TT + t) * CC);
    const float4* awr = (const float4*)atten_w;

    float4 wf4[4], aw4[4];
#pragma unroll
    for (int i = 0; i < 4; i++) {
        wf4[i] = wfr[lane + 32 * i];
        aw4[i] = awr[lane + 32 * i];
    }
    const float bsc = atten_b[0];

    for (int l = 0; l < LL; l++) {
        const float4* pr = (const float4*)(pos_emb + l * CC);
        float acc = 0.f;
#pragma unroll
        for (int i = 0; i < 4; i++) {
            float4 p = pr[lane + 32 * i];
            acc = fmaf(fast_tanh(wf4[i].x + p.x), aw4[i].x, acc);
            acc = fmaf(fast_tanh(wf4[i].y + p.y), aw4[i].y, acc);
            acc = fmaf(fast_tanh(wf4[i].z + p.z), aw4[i].z, acc);
            acc = fmaf(fast_tanh(wf4[i].w + p.w), aw4[i].w, acc);
        }
#pragma unroll
        for (int s = 16; s; s >>= 1) acc += __shfl_xor_sync(0xffffffffu, acc, s);
        if (lane == 0) g_scores[(b * LL + l) * TT + t] = acc + bsc;
    }
}

// ---------------------------------------------------------------------------
// Kernel B2: softmax over t, then pvam[b,l,c] = sum_t attn[l,t] * wf[b,t,c]
// grid = (C/256, B), 256 threads. attn in smem; thread owns one column c.
// ---------------------------------------------------------------------------
__global__ __launch_bounds__(256) void pvam_kernel(float* __restrict__ out)
{
    __shared__ float attn_s[LL * TT];  // 25.6 KB
    const int b = blockIdx.y;
    const int tid = threadIdx.x;
    const int warp = tid >> 5;
    const int lane = tid & 31;

    // Softmax: one warp per l (looped)
    for (int l = warp; l < LL; l += 8) {
        const float* sr = g_scores + (b * LL + l) * TT;
        float v[8];
        float m = -1e30f;
#pragma unroll
        for (int i = 0; i < 8; i++) {
            v[i] = sr[lane + 32 * i];
            m = fmaxf(m, v[i]);
        }
#pragma unroll
        for (int s = 16; s; s >>= 1) m = fmaxf(m, __shfl_xor_sync(0xffffffffu, m, s));
        float ssum = 0.f;
#pragma unroll
        for (int i = 0; i < 8; i++) {
            float e = __expf(v[i] - m);
            attn_s[l * TT + lane + 32 * i] = e;
            ssum += e;
        }
#pragma unroll
        for (int s = 16; s; s >>= 1) ssum += __shfl_xor_sync(0xffffffffu, ssum, s);
        float inv = __fdividef(1.f, ssum);
#pragma unroll
        for (int i = 0; i < 8; i++) attn_s[l * TT + lane + 32 * i] *= inv;
    }
    __syncthreads();

    // Weighted sum over t: thread owns one column c, 25 accumulators
    const int c = blockIdx.x * 256 + tid;
    const float* wfb = g_wf + (b * TT) * CC + c;
    float acc[LL];
#pragma unroll
    for (int l = 0; l < LL; l++) acc[l] = 0.f;

    for (int t = 0; t < TT; t++) {
        float w = wfb[t * CC];
#pragma unroll
        for (int l = 0; l < LL; l++)
            acc[l] = fmaf(attn_s[l * TT + t], w, acc[l]);
    }

    float* o = out + (b * LL) * CC + c;
#pragma unroll
    for (int l = 0; l < LL; l++) o[l * CC] = acc[l];
}

// ---------------------------------------------------------------------------
extern "C" void kernel_launch(void* const* d_in, const int* in_sizes, int n_in,
                              void* d_out, int out_size)
{
    const float* word_features = (const float*)d_in[0];  // (32,256,512)
    const float* word_fc_w     = (const float*)d_in[1];  // (512,512)
    const float* word_fc_b     = (const float*)d_in[2];  // (512,)
    const float* pos_emb       = (const float*)d_in[3];  // (25,512)
    const float* atten_w       = (const float*)d_in[4];  // (512,)
    const float* atten_b       = (const float*)d_in[5];  // (1,)
    float* out = (float*)d_out;                          // (32,25,512)

    wf_gemm_kernel<<<dim3(CC / 128, (BB * TT) / 128), 256>>>(
        word_features, word_fc_w, word_fc_b);
    scores_kernel<<<dim3(TT / 8, BB), 256>>>(pos_emb, atten_w, atten_b);
    pvam_kernel<<<dim3(CC / 256, BB), 256>>>(out);
}

// round 2
// speedup vs baseline: 1.6006x; 1.6006x over previous
#include <cuda_runtime.h>
#include <cuda_bf16.h>
#include <cstdint>

// Problem constants (fixed by reference)
#define BB 32
#define TT 256
#define CC 512
#define LL 25

// Scratch in device globals (no allocations allowed in kernel_launch)
__device__ float g_wf[BB * TT * CC];        // 16 MB: post-FC features
__device__ float g_scores[BB * LL * TT];    // 0.8 MB: attention logits

// ---------------------------------------------------------------------------
// HW tanh (MUFU.TANH, sm_75+): 1 op vs ~14 FFMA for the rational version.
// ---------------------------------------------------------------------------
__device__ __forceinline__ float htanh(float x) {
    float y;
    asm("tanh.approx.f32 %0, %1;" : "=f"(y) : "f"(x));
    return y;
}

// fp32 -> tf32 with round-to-nearest (unbiased; keeps error ~2^-12 relative)
__device__ __forceinline__ float to_tf32(float x) {
    uint32_t u;
    asm("cvt.rna.tf32.f32 %0, %1;" : "=r"(u) : "f"(x));
    return __uint_as_float(u);
}

// ---------------------------------------------------------------------------
// Kernel A: wf[m,n] = sum_k X[m,k] * W[n,k] + bias[n]   (tf32 tensor cores)
// M=8192, N=512, K=512. Block tile 128x128, BK=16, double-buffered smem.
// 8 warps: warp tile 64(m) x 32(n) = 4x4 mma.m16n8k8 tiles per k8 step.
// ---------------------------------------------------------------------------
__global__ __launch_bounds__(256) void wf_gemm_tf32(
    const float* __restrict__ X,     // [8192, 512]
    const float* __restrict__ W,     // [512, 512] (row n, col k)
    const float* __restrict__ bias)  // [512]
{
    __shared__ float As[2][128][20];   // pad 20: conflict-free LDS + STS.128
    __shared__ float Bs[2][128][20];

    const int tid  = threadIdx.x;
    const int lane = tid & 31;
    const int warp = tid >> 5;
    const int g    = lane >> 2;          // group id 0..7
    const int tg   = lane & 3;           // thread-in-group 0..3
    const int wm   = (warp >> 2) << 6;   // 0, 64
    const int wn   = (warp & 3) << 5;    // 0, 32, 64, 96

    const int m0 = blockIdx.y << 7;
    const int n0 = blockIdx.x << 7;

    const int lr = tid >> 2;             // 0..63 (row within tile, +64 second half)
    const int lc = (tid & 3) << 2;       // 0, 4, 8, 12

    const float* Ag = X + (m0 + lr) * CC + lc;
    const float* Bg = W + (n0 + lr) * CC + lc;

    float acc[4][4][4];
#pragma unroll
    for (int mt = 0; mt < 4; mt++)
#pragma unroll
        for (int nt = 0; nt < 4; nt++)
#pragma unroll
            for (int i = 0; i < 4; i++) acc[mt][nt][i] = 0.f;

    float4 pa0, pa1, pb0, pb1;

#define GEMM_STORE_TILE(SS)                                                  \
    do {                                                                     \
        float4 t;                                                            \
        t.x = to_tf32(pa0.x); t.y = to_tf32(pa0.y);                          \
        t.z = to_tf32(pa0.z); t.w = to_tf32(pa0.w);                          \
        *(float4*)&As[SS][lr][lc] = t;                                       \
        t.x = to_tf32(pa1.x); t.y = to_tf32(pa1.y);                          \
        t.z = to_tf32(pa1.z); t.w = to_tf32(pa1.w);                          \
        *(float4*)&As[SS][lr + 64][lc] = t;                                  \
        t.x = to_tf32(pb0.x); t.y = to_tf32(pb0.y);                          \
        t.z = to_tf32(pb0.z); t.w = to_tf32(pb0.w);                          \
        *(float4*)&Bs[SS][lr][lc] = t;                                       \
        t.x = to_tf32(pb1.x); t.y = to_tf32(pb1.y);                          \
        t.z = to_tf32(pb1.z); t.w = to_tf32(pb1.w);                          \
        *(float4*)&Bs[SS][lr + 64][lc] = t;                                  \
    } while (0)

    // prologue: tile 0
    pa0 = *(const float4*)(Ag);
    pa1 = *(const float4*)(Ag + 64 * CC);
    pb0 = *(const float4*)(Bg);
    pb1 = *(const float4*)(Bg + 64 * CC);
    GEMM_STORE_TILE(0);
    __syncthreads();

    int s = 0;
    for (int it = 0; it < 32; ++it) {
        if (it < 31) {
            const int ko = (it + 1) << 4;
            pa0 = *(const float4*)(Ag + ko);
            pa1 = *(const float4*)(Ag + 64 * CC + ko);
            pb0 = *(const float4*)(Bg + ko);
            pb1 = *(const float4*)(Bg + 64 * CC + ko);
        }
#pragma unroll
        for (int kk = 0; kk < 16; kk += 8) {
            uint32_t af[4][4], bf[4][2];
#pragma unroll
            for (int mt = 0; mt < 4; mt++) {
                const int r = wm + (mt << 4) + g;
                af[mt][0] = __float_as_uint(As[s][r][kk + tg]);
                af[mt][1] = __float_as_uint(As[s][r + 8][kk + tg]);
                af[mt][2] = __float_as_uint(As[s][r][kk + tg + 4]);
                af[mt][3] = __float_as_uint(As[s][r + 8][kk + tg + 4]);
            }
#pragma unroll
            for (int nt = 0; nt < 4; nt++) {
                const int r = wn + (nt << 3) + g;
                bf[nt][0] = __float_as_uint(Bs[s][r][kk + tg]);
                bf[nt][1] = __float_as_uint(Bs[s][r][kk + tg + 4]);
            }
#pragma unroll
            for (int mt = 0; mt < 4; mt++)
#pragma unroll
                for (int nt = 0; nt < 4; nt++) {
                    asm volatile(
                        "mma.sync.aligned.m16n8k8.row.col.f32.tf32.tf32.f32 "
                        "{%0,%1,%2,%3}, {%4,%5,%6,%7}, {%8,%9}, {%0,%1,%2,%3};"
                        : "+f"(acc[mt][nt][0]), "+f"(acc[mt][nt][1]),
                          "+f"(acc[mt][nt][2]), "+f"(acc[mt][nt][3])
                        : "r"(af[mt][0]), "r"(af[mt][1]),
                          "r"(af[mt][2]), "r"(af[mt][3]),
                          "r"(bf[nt][0]), "r"(bf[nt][1]));
                }
        }
        if (it < 31) {
            const int ns = s ^ 1;
            GEMM_STORE_TILE(ns);
            __syncthreads();
            s = ns;
        }
    }

    // Epilogue: add bias, store.
    // C frag: c0:(g, 2tg) c1:(g, 2tg+1) c2:(g+8, 2tg) c3:(g+8, 2tg+1)
#pragma unroll
    for (int nt = 0; nt < 4; nt++) {
        const int n = n0 + wn + (nt << 3) + (tg << 1);
        const float b0v = bias[n];
        const float b1v = bias[n + 1];
#pragma unroll
        for (int mt = 0; mt < 4; mt++) {
            const int m = m0 + wm + (mt << 4) + g;
            float2 v0 = make_float2(acc[mt][nt][0] + b0v, acc[mt][nt][1] + b1v);
            float2 v1 = make_float2(acc[mt][nt][2] + b0v, acc[mt][nt][3] + b1v);
            *(float2*)&g_wf[m * CC + n]       = v0;
            *(float2*)&g_wf[(m + 8) * CC + n] = v1;
        }
    }
#undef GEMM_STORE_TILE
}

// ---------------------------------------------------------------------------
// Kernel B1: scores[b,l,t] = sum_c tanh(wf[b,t,c] + pos[l,c]) * aw[c] + ab
// One warp per (b,t) row; wf + atten_w live in registers for all 25 l's.
// tanh via MUFU.TANH. grid = (T/8, B), 256 threads.
// ---------------------------------------------------------------------------
__global__ __launch_bounds__(256) void scores_kernel(
    const float* __restrict__ pos_emb,   // [25, 512]
    const float* __restrict__ atten_w,   // [512]
    const float* __restrict__ atten_b)   // [1]
{
    const int warp = threadIdx.x >> 5;
    const int lane = threadIdx.x & 31;
    const int b = blockIdx.y;
    const int t = blockIdx.x * 8 + warp;

    const float4* wfr = (const float4*)(g_wf + (b * TT + t) * CC);
    const float4* awr = (const float4*)atten_w;

    float4 wf4[4], aw4[4];
#pragma unroll
    for (int i = 0; i < 4; i++) {
        wf4[i] = wfr[lane + 32 * i];
        aw4[i] = awr[lane + 32 * i];
    }
    const float bsc = atten_b[0];

    for (int l = 0; l < LL; l++) {
        const float4* pr = (const float4*)(pos_emb + l * CC);
        float acc = 0.f;
#pragma unroll
        for (int i = 0; i < 4; i++) {
            float4 p = pr[lane + 32 * i];
            acc = fmaf(htanh(wf4[i].x + p.x), aw4[i].x, acc);
            acc = fmaf(htanh(wf4[i].y + p.y), aw4[i].y, acc);
            acc = fmaf(htanh(wf4[i].z + p.z), aw4[i].z, acc);
            acc = fmaf(htanh(wf4[i].w + p.w), aw4[i].w, acc);
        }
#pragma unroll
        for (int s = 16; s; s >>= 1) acc += __shfl_xor_sync(0xffffffffu, acc, s);
        if (lane == 0) g_scores[(b * LL + l) * TT + t] = acc + bsc;
    }
}

// ---------------------------------------------------------------------------
// Kernel B2: softmax over t, then pvam[b,l,c] = sum_t attn[l,t] * wf[b,t,c]
// grid = (C/256, B), 256 threads. attn in smem; thread owns one column c.
// ---------------------------------------------------------------------------
__global__ __launch_bounds__(256) void pvam_kernel(float* __restrict__ out)
{
    __shared__ float attn_s[LL * TT];  // 25.6 KB
    const int b = blockIdx.y;
    const int tid = threadIdx.x;
    const int warp = tid >> 5;
    const int lane = tid & 31;

    // Softmax: one warp per l (looped)
    for (int l = warp; l < LL; l += 8) {
        const float* sr = g_scores + (b * LL + l) * TT;
        float v[8];
        float m = -1e30f;
#pragma unroll
        for (int i = 0; i < 8; i++) {
            v[i] = sr[lane + 32 * i];
            m = fmaxf(m, v[i]);
        }
#pragma unroll
        for (int s = 16; s; s >>= 1) m = fmaxf(m, __shfl_xor_sync(0xffffffffu, m, s));
        float ssum = 0.f;
#pragma unroll
        for (int i = 0; i < 8; i++) {
            float e = __expf(v[i] - m);
            attn_s[l * TT + lane + 32 * i] = e;
            ssum += e;
        }
#pragma unroll
        for (int s = 16; s; s >>= 1) ssum += __shfl_xor_sync(0xffffffffu, ssum, s);
        float inv = __fdividef(1.f, ssum);
#pragma unroll
        for (int i = 0; i < 8; i++) attn_s[l * TT + lane + 32 * i] *= inv;
    }
    __syncthreads();

    // Weighted sum over t: thread owns one column c, 25 accumulators
    const int c = blockIdx.x * 256 + tid;
    const float* wfb = g_wf + (b * TT) * CC + c;
    float acc[LL];
#pragma unroll
    for (int l = 0; l < LL; l++) acc[l] = 0.f;

    for (int t = 0; t < TT; t++) {
        float w = wfb[t * CC];
#pragma unroll
        for (int l = 0; l < LL; l++)
            acc[l] = fmaf(attn_s[l * TT + t], w, acc[l]);
    }

    float* o = out + (b * LL) * CC + c;
#pragma unroll
    for (int l = 0; l < LL; l++) o[l * CC] = acc[l];
}

// ---------------------------------------------------------------------------
extern "C" void kernel_launch(void* const* d_in, const int* in_sizes, int n_in,
                              void* d_out, int out_size)
{
    const float* word_features = (const float*)d_in[0];  // (32,256,512)
    const float* word_fc_w     = (const float*)d_in[1];  // (512,512)
    const float* word_fc_b     = (const float*)d_in[2];  // (512,)
    const float* pos_emb       = (const float*)d_in[3];  // (25,512)
    const float* atten_w       = (const float*)d_in[4];  // (512,)
    const float* atten_b       = (const float*)d_in[5];  // (1,)
    float* out = (float*)d_out;                          // (32,25,512)

    wf_gemm_tf32<<<dim3(CC / 128, (BB * TT) / 128), 256>>>(
        word_features, word_fc_w, word_fc_b);
    scores_kernel<<<dim3(TT / 8, BB), 256>>>(pos_emb, atten_w, atten_b);
    pvam_kernel<<<dim3(CC / 256, BB), 256>>>(out);
}

// round 3
// speedup vs baseline: 2.5739x; 1.6081x over previous
#include <cuda_runtime.h>
#include <cuda_bf16.h>
#include <cstdint>

// Problem constants (fixed by reference)
#define BB 32
#define TT 256
#define CC 512
#define LL 25

// Scratch in device globals (no allocations allowed in kernel_launch)
__device__ float g_wf[BB * TT * CC];        // 16 MB: post-FC features
__device__ float g_scores[BB * LL * TT];    // 0.8 MB: attention logits

// ---------------------------------------------------------------------------
// HW tanh (MUFU.TANH)
// ---------------------------------------------------------------------------
__device__ __forceinline__ float htanh(float x) {
    float y;
    asm("tanh.approx.f32 %0, %1;" : "=f"(y) : "f"(x));
    return y;
}

// fp32 -> tf32 round-to-nearest
__device__ __forceinline__ float to_tf32(float x) {
    uint32_t u;
    asm("cvt.rna.tf32.f32 %0, %1;" : "=r"(u) : "f"(x));
    return __uint_as_float(u);
}

// ---------------------------------------------------------------------------
// Kernel A: wf[m,n] = sum_k X[m,k] * W[n,k] + bias[n]   (tf32 tensor cores)
// (unchanged from R1 — serves as control)
// ---------------------------------------------------------------------------
__global__ __launch_bounds__(256) void wf_gemm_tf32(
    const float* __restrict__ X,
    const float* __restrict__ W,
    const float* __restrict__ bias)
{
    __shared__ float As[2][128][20];
    __shared__ float Bs[2][128][20];

    const int tid  = threadIdx.x;
    const int lane = tid & 31;
    const int warp = tid >> 5;
    const int g    = lane >> 2;
    const int tg   = lane & 3;
    const int wm   = (warp >> 2) << 6;
    const int wn   = (warp & 3) << 5;

    const int m0 = blockIdx.y << 7;
    const int n0 = blockIdx.x << 7;

    const int lr = tid >> 2;
    const int lc = (tid & 3) << 2;

    const float* Ag = X + (m0 + lr) * CC + lc;
    const float* Bg = W + (n0 + lr) * CC + lc;

    float acc[4][4][4];
#pragma unroll
    for (int mt = 0; mt < 4; mt++)
#pragma unroll
        for (int nt = 0; nt < 4; nt++)
#pragma unroll
            for (int i = 0; i < 4; i++) acc[mt][nt][i] = 0.f;

    float4 pa0, pa1, pb0, pb1;

#define GEMM_STORE_TILE(SS)                                                  \
    do {                                                                     \
        float4 t;                                                            \
        t.x = to_tf32(pa0.x); t.y = to_tf32(pa0.y);                          \
        t.z = to_tf32(pa0.z); t.w = to_tf32(pa0.w);                          \
        *(float4*)&As[SS][lr][lc] = t;                                       \
        t.x = to_tf32(pa1.x); t.y = to_tf32(pa1.y);                          \
        t.z = to_tf32(pa1.z); t.w = to_tf32(pa1.w);                          \
        *(float4*)&As[SS][lr + 64][lc] = t;                                  \
        t.x = to_tf32(pb0.x); t.y = to_tf32(pb0.y);                          \
        t.z = to_tf32(pb0.z); t.w = to_tf32(pb0.w);                          \
        *(float4*)&Bs[SS][lr][lc] = t;                                       \
        t.x = to_tf32(pb1.x); t.y = to_tf32(pb1.y);                          \
        t.z = to_tf32(pb1.z); t.w = to_tf32(pb1.w);                          \
        *(float4*)&Bs[SS][lr + 64][lc] = t;                                  \
    } while (0)

    pa0 = *(const float4*)(Ag);
    pa1 = *(const float4*)(Ag + 64 * CC);
    pb0 = *(const float4*)(Bg);
    pb1 = *(const float4*)(Bg + 64 * CC);
    GEMM_STORE_TILE(0);
    __syncthreads();

    int s = 0;
    for (int it = 0; it < 32; ++it) {
        if (it < 31) {
            const int ko = (it + 1) << 4;
            pa0 = *(const float4*)(Ag + ko);
            pa1 = *(const float4*)(Ag + 64 * CC + ko);
            pb0 = *(const float4*)(Bg + ko);
            pb1 = *(const float4*)(Bg + 64 * CC + ko);
        }
#pragma unroll
        for (int kk = 0; kk < 16; kk += 8) {
            uint32_t af[4][4], bf[4][2];
#pragma unroll
            for (int mt = 0; mt < 4; mt++) {
                const int r = wm + (mt << 4) + g;
                af[mt][0] = __float_as_uint(As[s][r][kk + tg]);
                af[mt][1] = __float_as_uint(As[s][r + 8][kk + tg]);
                af[mt][2] = __float_as_uint(As[s][r][kk + tg + 4]);
                af[mt][3] = __float_as_uint(As[s][r + 8][kk + tg + 4]);
            }
#pragma unroll
            for (int nt = 0; nt < 4; nt++) {
                const int r = wn + (nt << 3) + g;
                bf[nt][0] = __float_as_uint(Bs[s][r][kk + tg]);
                bf[nt][1] = __float_as_uint(Bs[s][r][kk + tg + 4]);
            }
#pragma unroll
            for (int mt = 0; mt < 4; mt++)
#pragma unroll
                for (int nt = 0; nt < 4; nt++) {
                    asm volatile(
                        "mma.sync.aligned.m16n8k8.row.col.f32.tf32.tf32.f32 "
                        "{%0,%1,%2,%3}, {%4,%5,%6,%7}, {%8,%9}, {%0,%1,%2,%3};"
                        : "+f"(acc[mt][nt][0]), "+f"(acc[mt][nt][1]),
                          "+f"(acc[mt][nt][2]), "+f"(acc[mt][nt][3])
                        : "r"(af[mt][0]), "r"(af[mt][1]),
                          "r"(af[mt][2]), "r"(af[mt][3]),
                          "r"(bf[nt][0]), "r"(bf[nt][1]));
                }
        }
        if (it < 31) {
            const int ns = s ^ 1;
            GEMM_STORE_TILE(ns);
            __syncthreads();
            s = ns;
        }
    }

#pragma unroll
    for (int nt = 0; nt < 4; nt++) {
        const int n = n0 + wn + (nt << 3) + (tg << 1);
        const float b0v = bias[n];
        const float b1v = bias[n + 1];
#pragma unroll
        for (int mt = 0; mt < 4; mt++) {
            const int m = m0 + wm + (mt << 4) + g;
            float2 v0 = make_float2(acc[mt][nt][0] + b0v, acc[mt][nt][1] + b1v);
            float2 v1 = make_float2(acc[mt][nt][2] + b0v, acc[mt][nt][3] + b1v);
            *(float2*)&g_wf[m * CC + n]       = v0;
            *(float2*)&g_wf[(m + 8) * CC + n] = v1;
        }
    }
#undef GEMM_STORE_TILE
}

// ---------------------------------------------------------------------------
// Kernel B1 v2: scores[b,l,t] = sum_c tanh(wf[b,t,c]+pos[l,c])*aw[c] + ab
// One warp per TWO t-rows: each pos load feeds 2x the FMA/MUFU work.
// grid = (T/16, B), 256 threads (8 warps x 2 t each).
// ---------------------------------------------------------------------------
__global__ __launch_bounds__(256) void scores_kernel(
    const float* __restrict__ pos_emb,   // [25, 512]
    const float* __restrict__ atten_w,   // [512]
    const float* __restrict__ atten_b)   // [1]
{
    const int warp = threadIdx.x >> 5;
    const int lane = threadIdx.x & 31;
    const int b = blockIdx.y;
    const int t0 = blockIdx.x * 16 + warp * 2;

    const float4* wfr0 = (const float4*)(g_wf + (b * TT + t0) * CC);
    const float4* wfr1 = (const float4*)(g_wf + (b * TT + t0 + 1) * CC);
    const float4* awr  = (const float4*)atten_w;

    float4 wfA[4], wfB[4], aw4[4];
#pragma unroll
    for (int i = 0; i < 4; i++) {
        wfA[i] = wfr0[lane + 32 * i];
        wfB[i] = wfr1[lane + 32 * i];
        aw4[i] = awr[lane + 32 * i];
    }
    const float bsc = atten_b[0];

#pragma unroll 5
    for (int l = 0; l < LL; l++) {
        const float4* pr = (const float4*)(pos_emb + l * CC);
        float accA = 0.f, accB = 0.f;
#pragma unroll
        for (int i = 0; i < 4; i++) {
            float4 p = __ldg(&pr[lane + 32 * i]);
            accA = fmaf(htanh(wfA[i].x + p.x), aw4[i].x, accA);
            accB = fmaf(htanh(wfB[i].x + p.x), aw4[i].x, accB);
            accA = fmaf(htanh(wfA[i].y + p.y), aw4[i].y, accA);
            accB = fmaf(htanh(wfB[i].y + p.y), aw4[i].y, accB);
            accA = fmaf(htanh(wfA[i].z + p.z), aw4[i].z, accA);
            accB = fmaf(htanh(wfB[i].z + p.z), aw4[i].z, accB);
            accA = fmaf(htanh(wfA[i].w + p.w), aw4[i].w, accA);
            accB = fmaf(htanh(wfB[i].w + p.w), aw4[i].w, accB);
        }
#pragma unroll
        for (int s = 16; s; s >>= 1) {
            accA += __shfl_xor_sync(0xffffffffu, accA, s);
            accB += __shfl_xor_sync(0xffffffffu, accB, s);
        }
        if (lane == 0) {
            *(float2*)&g_scores[(b * LL + l) * TT + t0] =
                make_float2(accA + bsc, accB + bsc);
        }
    }
}

// ---------------------------------------------------------------------------
// Kernel B2 v2: softmax over t, then pvam[b,l,c] = sum_t attn[l,t]*wf[b,t,c]
// grid = (C/256, B), 256 threads. attn via float4 (4 t per LDS.128).
// ---------------------------------------------------------------------------
__global__ __launch_bounds__(256) void pvam_kernel(float* __restrict__ out)
{
    __shared__ float attn_s[LL * TT];  // 25.6 KB
    const int b = blockIdx.y;
    const int tid = threadIdx.x;
    const int warp = tid >> 5;
    const int lane = tid & 31;

    // Softmax: one warp per l (looped)
    for (int l = warp; l < LL; l += 8) {
        const float* sr = g_scores + (b * LL + l) * TT;
        float v[8];
        float m = -1e30f;
#pragma unroll
        for (int i = 0; i < 8; i++) {
            v[i] = sr[lane + 32 * i];
            m = fmaxf(m, v[i]);
        }
#pragma unroll
        for (int s = 16; s; s >>= 1) m = fmaxf(m, __shfl_xor_sync(0xffffffffu, m, s));
        float ssum = 0.f;
#pragma unroll
        for (int i = 0; i < 8; i++) {
            float e = __expf(v[i] - m);
            attn_s[l * TT + lane + 32 * i] = e;
            ssum += e;
        }
#pragma unroll
        for (int s = 16; s; s >>= 1) ssum += __shfl_xor_sync(0xffffffffu, ssum, s);
        float inv = __fdividef(1.f, ssum);
#pragma unroll
        for (int i = 0; i < 8; i++) attn_s[l * TT + lane + 32 * i] *= inv;
    }
    __syncthreads();

    // Weighted sum over t: thread owns column c; 4 t's per step via float4
    const int c = blockIdx.x * 256 + tid;
    const float* wfb = g_wf + (b * TT) * CC + c;
    float acc[LL];
#pragma unroll
    for (int l = 0; l < LL; l++) acc[l] = 0.f;

    for (int t4 = 0; t4 < TT; t4 += 4) {
        float w0 = wfb[(t4 + 0) * CC];
        float w1 = wfb[(t4 + 1) * CC];
        float w2 = wfb[(t4 + 2) * CC];
        float w3 = wfb[(t4 + 3) * CC];
#pragma unroll
        for (int l = 0; l < LL; l++) {
            float4 a = *(const float4*)&attn_s[l * TT + t4];
            float s0 = fmaf(a.x, w0, acc[l]);
            float s1 = fmaf(a.y, w1, s0);
            float s2 = fmaf(a.z, w2, s1);
            acc[l] = fmaf(a.w, w3, s2);
        }
    }

    float* o = out + (b * LL) * CC + c;
#pragma unroll
    for (int l = 0; l < LL; l++) o[l * CC] = acc[l];
}

// ---------------------------------------------------------------------------
extern "C" void kernel_launch(void* const* d_in, const int* in_sizes, int n_in,
                              void* d_out, int out_size)
{
    const float* word_features = (const float*)d_in[0];  // (32,256,512)
    const float* word_fc_w     = (const float*)d_in[1];  // (512,512)
    const float* word_fc_b     = (const float*)d_in[2];  // (512,)
    const float* pos_emb       = (const float*)d_in[3];  // (25,512)
    const float* atten_w       = (const float*)d_in[4];  // (512,)
    const float* atten_b       = (const float*)d_in[5];  // (1,)
    float* out = (float*)d_out;                          // (32,25,512)

    wf_gemm_tf32<<<dim3(CC / 128, (BB * TT) / 128), 256>>>(
        word_features, word_fc_w, word_fc_b);
    scores_kernel<<<dim3(TT / 16, BB), 256>>>(pos_emb, atten_w, atten_b);
    pvam_kernel<<<dim3(CC / 256, BB), 256>>>(out);
}

// round 5
// speedup vs baseline: 3.0356x; 1.1794x over previous
#include <cuda_runtime.h>
#include <cuda_fp16.h>
#include <cuda_bf16.h>
#include <cstdint>

// Problem constants (fixed by reference)
#define BB 32
#define TT 256
#define CC 512
#define LL 25

// Scratch in device globals (no allocations allowed in kernel_launch)
__device__ float g_wf[BB * TT * CC];        // 16 MB: post-FC features
__device__ float g_scores[BB * LL * TT];    // 0.8 MB: attention logits

// ---------------------------------------------------------------------------
__device__ __forceinline__ float htanh(float x) {
    float y;
    asm("tanh.approx.f32 %0, %1;" : "=f"(y) : "f"(x));
    return y;
}

// ---------------------------------------------------------------------------
// Kernel A: wf[m,n] = sum_k X[m,k] * W[n,k] + bias[n]
// fp16 tensor cores (m16n8k16, fp32 accum — same 11-bit mantissa as tf32).
// M=8192, N=512, K=512. Block 128x128, BK=16, double-buffered, 2 CTA/SM.
// SMEM rows padded to 24 halves (48B): fragment LDS bank = (g*12+tg)%32,
// all 32 lanes distinct -> conflict-free.
// ---------------------------------------------------------------------------
#define PADH 24
__global__ __launch_bounds__(256, 2) void wf_gemm_fp16(
    const float* __restrict__ X,     // [8192, 512]
    const float* __restrict__ W,     // [512, 512] (row n, col k)
    const float* __restrict__ bias)  // [512]
{
    __shared__ __half As[2][128][PADH];
    __shared__ __half Bs[2][128][PADH];

    const int tid  = threadIdx.x;
    const int lane = tid & 31;
    const int warp = tid >> 5;
    const int g    = lane >> 2;          // 0..7
    const int tg   = lane & 3;           // 0..3
    const int wm   = (warp >> 2) << 6;   // 0, 64
    const int wn   = (warp & 3) << 5;    // 0, 32, 64, 96

    const int m0 = blockIdx.y << 7;
    const int n0 = blockIdx.x << 7;

    const int lr = tid >> 2;             // 0..63
    const int lc = (tid & 3) << 2;       // 0, 4, 8, 12 (k offset)

    const float* Ag = X + (m0 + lr) * CC + lc;
    const float* Bg = W + (n0 + lr) * CC + lc;

    float acc[4][4][4];
#pragma unroll
    for (int mt = 0; mt < 4; mt++)
#pragma unroll
        for (int nt = 0; nt < 4; nt++)
#pragma unroll
            for (int i = 0; i < 4; i++) acc[mt][nt][i] = 0.f;

    float4 pa0, pa1, pb0, pb1;

#define CVT_STORE(dst, v)                                                     \
    do {                                                                      \
        __half2 h0 = __float22half2_rn(make_float2((v).x, (v).y));            \
        __half2 h1 = __float22half2_rn(make_float2((v).z, (v).w));            \
        *(uint2*)(dst) = make_uint2(*(uint32_t*)&h0, *(uint32_t*)&h1);        \
    } while (0)

#define GEMM_STORE_TILE(SS)                                                   \
    do {                                                                      \
        CVT_STORE(&As[SS][lr][lc], pa0);                                      \
        CVT_STORE(&As[SS][lr + 64][lc], pa1);                                 \
        CVT_STORE(&Bs[SS][lr][lc], pb0);                                      \
        CVT_STORE(&Bs[SS][lr + 64][lc], pb1);                                 \
    } while (0)

    // prologue: tile 0
    pa0 = *(const float4*)(Ag);
    pa1 = *(const float4*)(Ag + 64 * CC);
    pb0 = *(const float4*)(Bg);
    pb1 = *(const float4*)(Bg + 64 * CC);
    GEMM_STORE_TILE(0);
    __syncthreads();

    int s = 0;
    for (int it = 0; it < 32; ++it) {
        if (it < 31) {
            const int ko = (it + 1) << 4;
            pa0 = *(const float4*)(Ag + ko);
            pa1 = *(const float4*)(Ag + 64 * CC + ko);
            pb0 = *(const float4*)(Bg + ko);
            pb1 = *(const float4*)(Bg + 64 * CC + ko);
        }
        {
            uint32_t af[4][4], bf[4][2];
#pragma unroll
            for (int mt = 0; mt < 4; mt++) {
                const int r = wm + (mt << 4) + g;
                af[mt][0] = *(const uint32_t*)&As[s][r][2 * tg];
                af[mt][1] = *(const uint32_t*)&As[s][r + 8][2 * tg];
                af[mt][2] = *(const uint32_t*)&As[s][r][2 * tg + 8];
                af[mt][3] = *(const uint32_t*)&As[s][r + 8][2 * tg + 8];
            }
#pragma unroll
            for (int nt = 0; nt < 4; nt++) {
                const int r = wn + (nt << 3) + g;
                bf[nt][0] = *(const uint32_t*)&Bs[s][r][2 * tg];
                bf[nt][1] = *(const uint32_t*)&Bs[s][r][2 * tg + 8];
            }
#pragma unroll
            for (int mt = 0; mt < 4; mt++)
#pragma unroll
                for (int nt = 0; nt < 4; nt++) {
                    asm volatile(
                        "mma.sync.aligned.m16n8k16.row.col.f32.f16.f16.f32 "
                        "{%0,%1,%2,%3}, {%4,%5,%6,%7}, {%8,%9}, {%0,%1,%2,%3};"
                        : "+f"(acc[mt][nt][0]), "+f"(acc[mt][nt][1]),
                          "+f"(acc[mt][nt][2]), "+f"(acc[mt][nt][3])
                        : "r"(af[mt][0]), "r"(af[mt][1]),
                          "r"(af[mt][2]), "r"(af[mt][3]),
                          "r"(bf[nt][0]), "r"(bf[nt][1]));
                }
        }
        if (it < 31) {
            const int ns = s ^ 1;
            GEMM_STORE_TILE(ns);
            __syncthreads();
            s = ns;
        }
    }

    // Epilogue: add bias, store.
    // C frag: c0:(g,2tg) c1:(g,2tg+1) c2:(g+8,2tg) c3:(g+8,2tg+1)
#pragma unroll
    for (int nt = 0; nt < 4; nt++) {
        const int n = n0 + wn + (nt << 3) + (tg << 1);
        const float b0v = bias[n];
        const float b1v = bias[n + 1];
#pragma unroll
        for (int mt = 0; mt < 4; mt++) {
            const int m = m0 + wm + (mt << 4) + g;
            float2 v0 = make_float2(acc[mt][nt][0] + b0v, acc[mt][nt][1] + b1v);
            float2 v1 = make_float2(acc[mt][nt][2] + b0v, acc[mt][nt][3] + b1v);
            *(float2*)&g_wf[m * CC + n]       = v0;
            *(float2*)&g_wf[(m + 8) * CC + n] = v1;
        }
    }
#undef GEMM_STORE_TILE
#undef CVT_STORE
}

// ---------------------------------------------------------------------------
// Kernel B1 v3: scores[b,l,t] = sum_c tanh(wf[b,t,c]+pos[l,c])*aw[c] + ab
// One warp per FOUR t-rows: each pos load feeds 4x work; float4 output store.
// grid = (T/32, B), 256 threads (8 warps x 4 t each).
// ---------------------------------------------------------------------------
__global__ __launch_bounds__(256) void scores_kernel(
    const float* __restrict__ pos_emb,   // [25, 512]
    const float* __restrict__ atten_w,   // [512]
    const float* __restrict__ atten_b)   // [1]
{
    const int warp = threadIdx.x >> 5;
    const int lane = threadIdx.x & 31;
    const int b = blockIdx.y;
    const int t0 = blockIdx.x * 32 + warp * 4;

    const float4* awr = (const float4*)atten_w;

    float4 wf[4][4], aw4[4];
#pragma unroll
    for (int r = 0; r < 4; r++) {
        const float4* wfr = (const float4*)(g_wf + (b * TT + t0 + r) * CC);
#pragma unroll
        for (int i = 0; i < 4; i++) wf[r][i] = wfr[lane + 32 * i];
    }
#pragma unroll
    for (int i = 0; i < 4; i++) aw4[i] = awr[lane + 32 * i];
    const float bsc = atten_b[0];

#pragma unroll 2
    for (int l = 0; l < LL; l++) {
        const float4* pr = (const float4*)(pos_emb + l * CC);
        float acc0 = 0.f, acc1 = 0.f, acc2 = 0.f, acc3 = 0.f;
#pragma unroll
        for (int i = 0; i < 4; i++) {
            float4 p = __ldg(&pr[lane + 32 * i]);
            acc0 = fmaf(htanh(wf[0][i].x + p.x), aw4[i].x, acc0);
            acc1 = fmaf(htanh(wf[1][i].x + p.x), aw4[i].x, acc1);
            acc2 = fmaf(htanh(wf[2][i].x + p.x), aw4[i].x, acc2);
            acc3 = fmaf(htanh(wf[3][i].x + p.x), aw4[i].x, acc3);
            acc0 = fmaf(htanh(wf[0][i].y + p.y), aw4[i].y, acc0);
            acc1 = fmaf(htanh(wf[1][i].y + p.y), aw4[i].y, acc1);
            acc2 = fmaf(htanh(wf[2][i].y + p.y), aw4[i].y, acc2);
            acc3 = fmaf(htanh(wf[3][i].y + p.y), aw4[i].y, acc3);
            acc0 = fmaf(htanh(wf[0][i].z + p.z), aw4[i].z, acc0);
            acc1 = fmaf(htanh(wf[1][i].z + p.z), aw4[i].z, acc1);
            acc2 = fmaf(htanh(wf[2][i].z + p.z), aw4[i].z, acc2);
            acc3 = fmaf(htanh(wf[3][i].z + p.z), aw4[i].z, acc3);
            acc0 = fmaf(htanh(wf[0][i].w + p.w), aw4[i].w, acc0);
            acc1 = fmaf(htanh(wf[1][i].w + p.w), aw4[i].w, acc1);
            acc2 = fmaf(htanh(wf[2][i].w + p.w), aw4[i].w, acc2);
            acc3 = fmaf(htanh(wf[3][i].w + p.w), aw4[i].w, acc3);
        }
#pragma unroll
        for (int s = 16; s; s >>= 1) {
            acc0 += __shfl_xor_sync(0xffffffffu, acc0, s);
            acc1 += __shfl_xor_sync(0xffffffffu, acc1, s);
            acc2 += __shfl_xor_sync(0xffffffffu, acc2, s);
            acc3 += __shfl_xor_sync(0xffffffffu, acc3, s);
        }
        if (lane == 0) {
            *(float4*)&g_scores[(b * LL + l) * TT + t0] =
                make_float4(acc0 + bsc, acc1 + bsc, acc2 + bsc, acc3 + bsc);
        }
    }
}

// ---------------------------------------------------------------------------
// Kernel B2: softmax over t, then pvam[b,l,c] = sum_t attn[l,t]*wf[b,t,c]
// grid = (C/256, B), 256 threads. attn via float4 (4 t per LDS.128).
// ---------------------------------------------------------------------------
__global__ __launch_bounds__(256) void pvam_kernel(float* __restrict__ out)
{
    __shared__ float attn_s[LL * TT];  // 25.6 KB
    const int b = blockIdx.y;
    const int tid = threadIdx.x;
    const int warp = tid >> 5;
    const int lane = tid & 31;

    for (int l = warp; l < LL; l += 8) {
        const float* sr = g_scores + (b * LL + l) * TT;
        float v[8];
        float m = -1e30f;
#pragma unroll
        for (int i = 0; i < 8; i++) {
            v[i] = sr[lane + 32 * i];
            m = fmaxf(m, v[i]);
        }
#pragma unroll
        for (int s = 16; s; s >>= 1) m = fmaxf(m, __shfl_xor_sync(0xffffffffu, m, s));
        float ssum = 0.f;
#pragma unroll
        for (int i = 0; i < 8; i++) {
            float e = __expf(v[i] - m);
            attn_s[l * TT + lane + 32 * i] = e;
            ssum += e;
        }
#pragma unroll
        for (int s = 16; s; s >>= 1) ssum += __shfl_xor_sync(0xffffffffu, ssum, s);
        float inv = __fdividef(1.f, ssum);
#pragma unroll
        for (int i = 0; i < 8; i++) attn_s[l * TT + lane + 32 * i] *= inv;
    }
    __syncthreads();

    const int c = blockIdx.x * 256 + tid;
    const float* wfb = g_wf + (b * TT) * CC + c;
    float acc[LL];
#pragma unroll
    for (int l = 0; l < LL; l++) acc[l] = 0.f;

    for (int t4 = 0; t4 < TT; t4 += 4) {
        float w0 = wfb[(t4 + 0) * CC];
        float w1 = wfb[(t4 + 1) * CC];
        float w2 = wfb[(t4 + 2) * CC];
        float w3 = wfb[(t4 + 3) * CC];
#pragma unroll
        for (int l = 0; l < LL; l++) {
            float4 a = *(const float4*)&attn_s[l * TT + t4];
            float s0 = fmaf(a.x, w0, acc[l]);
            float s1 = fmaf(a.y, w1, s0);
            float s2 = fmaf(a.z, w2, s1);
            acc[l] = fmaf(a.w, w3, s2);
        }
    }

    float* o = out + (b * LL) * CC + c;
#pragma unroll
    for (int l = 0; l < LL; l++) o[l * CC] = acc[l];
}

// ---------------------------------------------------------------------------
extern "C" void kernel_launch(void* const* d_in, const int* in_sizes, int n_in,
                              void* d_out, int out_size)
{
    const float* word_features = (const float*)d_in[0];  // (32,256,512)
    const float* word_fc_w     = (const float*)d_in[1];  // (512,512)
    const float* word_fc_b     = (const float*)d_in[2];  // (512,)
    const float* pos_emb       = (const float*)d_in[3];  // (25,512)
    const float* atten_w       = (const float*)d_in[4];  // (512,)
    const float* atten_b       = (const float*)d_in[5];  // (1,)
    float* out = (float*)d_out;                          // (32,25,512)

    wf_gemm_fp16<<<dim3(CC / 128, (BB * TT) / 128), 256>>>(
        word_features, word_fc_w, word_fc_b);
    scores_kernel<<<dim3(TT / 32, BB), 256>>>(pos_emb, atten_w, atten_b);
    pvam_kernel<<<dim3(CC / 256, BB), 256>>>(out);
}